// round 1
// baseline (speedup 1.0000x reference)
#include <cuda_runtime.h>

#define BB    64
#define CIN   64
#define HH    56
#define WW    56
#define CHN   512
#define IN_DIM (CIN*HH*WW)      // 200704
#define NKEEP 128
#define SPLITK 64
#define KC (IN_DIM/SPLITK)      // 3136

// Scratch (no allocations allowed -> __device__ globals)
__device__ float g_partial[SPLITK * BB * CHN];  // [s][m][n]  8 MB
__device__ float g_scores[BB * CHN];
__device__ int   g_idx[BB * NKEEP];

// ---------------------------------------------------------------------------
// Kernel 1: router GEMM partials. scores[m,n] = sum_k x[m,k]*rw[n,k]
// Split-K: grid = (8 n-tiles, 64 k-splits). Block 256 threads, 64x64 tile,
// 4x4 per-thread micro-tile, BK=16 smem staging.
// ---------------------------------------------------------------------------
__global__ __launch_bounds__(256) void router_gemm(const float* __restrict__ x,
                                                   const float* __restrict__ rw) {
    const int nt = blockIdx.x;   // 0..7
    const int s  = blockIdx.y;   // 0..63
    __shared__ float As[16][68];
    __shared__ float Bs[16][68];

    const int tid = threadIdx.x;
    const int tx = tid & 15;     // n-tile lane
    const int ty = tid >> 4;     // m-tile lane
    const int lm = tid >> 2;     // 0..63 row for loads
    const int lk = (tid & 3) * 4;

    const float* xp = x  + (size_t)lm * IN_DIM + (size_t)s * KC;
    const float* wp = rw + (size_t)(nt * 64 + lm) * IN_DIM + (size_t)s * KC;

    float acc[4][4];
#pragma unroll
    for (int i = 0; i < 4; i++)
#pragma unroll
        for (int j = 0; j < 4; j++) acc[i][j] = 0.f;

    for (int k0 = 0; k0 < KC; k0 += 16) {
        float4 av = *(const float4*)(xp + k0 + lk);
        float4 bv = *(const float4*)(wp + k0 + lk);
        __syncthreads();
        As[lk + 0][lm] = av.x; As[lk + 1][lm] = av.y;
        As[lk + 2][lm] = av.z; As[lk + 3][lm] = av.w;
        Bs[lk + 0][lm] = bv.x; Bs[lk + 1][lm] = bv.y;
        Bs[lk + 2][lm] = bv.z; Bs[lk + 3][lm] = bv.w;
        __syncthreads();
#pragma unroll
        for (int kk = 0; kk < 16; kk++) {
            float4 a = *(const float4*)&As[kk][ty * 4];
            float4 b = *(const float4*)&Bs[kk][tx * 4];
            float am[4] = {a.x, a.y, a.z, a.w};
            float bn[4] = {b.x, b.y, b.z, b.w};
#pragma unroll
            for (int i = 0; i < 4; i++)
#pragma unroll
                for (int j = 0; j < 4; j++) acc[i][j] += am[i] * bn[j];
        }
    }
    // store partial: layout [s][m][n], vectorized along n
#pragma unroll
    for (int i = 0; i < 4; i++) {
        int m = ty * 4 + i;
        int n = nt * 64 + tx * 4;
        float4 v = make_float4(acc[i][0], acc[i][1], acc[i][2], acc[i][3]);
        *(float4*)&g_partial[((size_t)s * BB + m) * CHN + n] = v;
    }
}

// ---------------------------------------------------------------------------
// Kernel 2: reduce split-K partials + bias -> g_scores[m][n]
// ---------------------------------------------------------------------------
__global__ void reduce_scores(const float* __restrict__ rb) {
    int t = blockIdx.x * 256 + threadIdx.x;   // 0 .. 64*512-1
    int m = t >> 9;
    int n = t & 511;
    float sum = rb[n];
    for (int s = 0; s < SPLITK; s++)
        sum += g_partial[((size_t)s * BB + m) * CHN + n];
    g_scores[t] = sum;
}

// ---------------------------------------------------------------------------
// Kernel 3: per-row stable top-128 by |score| -> sorted channel indices.
// rank_i = #{j : |s_j|>|s_i| or (|s_j|==|s_i| and j<i)}  (jax top_k tie rule)
// keep if rank < 128; compaction preserves ascending channel order (== sort).
// ---------------------------------------------------------------------------
__global__ __launch_bounds__(CHN) void select_topk() {
    __shared__ float sa[CHN];
    __shared__ unsigned char keep[CHN];
    const int m = blockIdx.x;
    const int i = threadIdx.x;
    float v = fabsf(g_scores[m * CHN + i]);
    sa[i] = v;
    __syncthreads();
    int rank = 0;
    for (int j = 0; j < CHN; j++) {
        float u = sa[j];
        rank += (u > v) || (u == v && j < i);
    }
    keep[i] = (rank < NKEEP) ? 1 : 0;
    __syncthreads();
    if (keep[i]) {
        int pos = 0;
        for (int j = 0; j < i; j++) pos += keep[j];
        g_idx[m * NKEEP + pos] = i;
    }
}

// ---------------------------------------------------------------------------
// Kernel 4: direct 3x3 conv for the 128 SELECTED channels only.
// Block = (h-tile of 8 rows, group of 4 selected channels, batch b).
// 64 threads; compute threads: 14 col-groups x 4 row-groups = 56, each owns a
// 4(chan) x 2(row) x 4(col) register tile -> 288 FMA per 60 LDS per ci step.
// x slab staged in smem per 8-input-channel chunk with halo + zero padding.
// ---------------------------------------------------------------------------
__global__ __launch_bounds__(64) void conv_sel(const float* __restrict__ x,
                                               const float* __restrict__ cw,
                                               const float* __restrict__ cb,
                                               float* __restrict__ out) {
    const int ht = blockIdx.x;   // 0..6   h0 = ht*8
    const int jg = blockIdx.y;   // 0..31  channels jg*4 .. jg*4+3
    const int b  = blockIdx.z;

    __shared__ float xs[8][10][58];   // [ci][row(+halo)][col(+halo)]
    __shared__ float ws[4][8][9];
    __shared__ int   cidx[4];
    __shared__ float cbias[4];

    const int tid = threadIdx.x;
    if (tid < 4) {
        int c = g_idx[b * NKEEP + jg * 4 + tid];
        cidx[tid]  = c;
        cbias[tid] = cb[c];
    }

    const int h0 = ht * 8;
    const int wc = tid % 14;   // col group  (4 cols)
    const int hr = tid / 14;   // row group  (2 rows)

    float acc[4][2][4];
#pragma unroll
    for (int ch = 0; ch < 4; ch++)
#pragma unroll
        for (int r = 0; r < 2; r++)
#pragma unroll
            for (int c = 0; c < 4; c++) acc[ch][r][c] = 0.f;

    for (int c0 = 0; c0 < CIN; c0 += 8) {
        __syncthreads();
        // stage x slab: 8 ci x 10 rows x 58 cols, zero-padded halo
        for (int i = tid; i < 8 * 10 * 58; i += 64) {
            int ci  = i / 580;
            int rem = i - ci * 580;
            int r   = rem / 58;
            int col = rem - r * 58;
            int h  = h0 - 1 + r;
            int w  = col - 1;
            float v = 0.f;
            if ((unsigned)h < (unsigned)HH && (unsigned)w < (unsigned)WW)
                v = x[(((size_t)b * CIN + c0 + ci) * HH + h) * WW + w];
            xs[ci][r][col] = v;
        }
        // stage weights: 4 chans x 8 ci x 9 taps
        for (int i = tid; i < 288; i += 64) {
            int ch  = i / 72;
            int rem = i - ch * 72;
            ws[ch][rem / 9][rem % 9] =
                cw[((size_t)cidx[ch] * CIN + c0) * 9 + rem];
        }
        __syncthreads();

        if (tid < 56) {
#pragma unroll
            for (int ci = 0; ci < 8; ci++) {
                float xv[4][6];
                const float* xr = &xs[ci][hr * 2][wc * 4];
#pragma unroll
                for (int r = 0; r < 4; r++)
#pragma unroll
                    for (int c = 0; c < 6; c++) xv[r][c] = xr[r * 58 + c];
#pragma unroll
                for (int ch = 0; ch < 4; ch++) {
#pragma unroll
                    for (int kh = 0; kh < 3; kh++)
#pragma unroll
                        for (int kw = 0; kw < 3; kw++) {
                            float wv = ws[ch][ci][kh * 3 + kw];
#pragma unroll
                            for (int r = 0; r < 2; r++)
#pragma unroll
                                for (int c = 0; c < 4; c++)
                                    acc[ch][r][c] += wv * xv[r + kh][c + kw];
                        }
                }
            }
        }
    }

    if (tid < 56) {
#pragma unroll
        for (int ch = 0; ch < 4; ch++) {
            int j = jg * 4 + ch;
            float bias = cbias[ch];
#pragma unroll
            for (int r = 0; r < 2; r++) {
                int h = h0 + hr * 2 + r;
                float* op = out + (((size_t)b * NKEEP + j) * HH + h) * WW + wc * 4;
#pragma unroll
                for (int c = 0; c < 4; c++) op[c] = acc[ch][r][c] + bias;
            }
        }
    }
}

// ---------------------------------------------------------------------------
extern "C" void kernel_launch(void* const* d_in, const int* in_sizes, int n_in,
                              void* d_out, int out_size) {
    const float* x  = (const float*)d_in[0];   // [64,64,56,56]
    const float* cw = (const float*)d_in[1];   // [4,128,64,3,3] == [512,64,3,3]
    const float* cb = (const float*)d_in[2];   // [4,128] == [512]
    const float* rw = (const float*)d_in[3];   // [512, 200704]
    const float* rb = (const float*)d_in[4];   // [512]
    float* out = (float*)d_out;                // [64,128,56,56]

    router_gemm<<<dim3(8, SPLITK), 256>>>(x, rw);
    reduce_scores<<<(BB * CHN) / 256, 256>>>(rb);
    select_topk<<<BB, CHN>>>();
    conv_sel<<<dim3(7, 32, BB), 64>>>(x, cw, cb, out);
}

// round 2
// speedup vs baseline: 1.0196x; 1.0196x over previous
#include <cuda_runtime.h>

#define BB    64
#define CIN   64
#define HH    56
#define WW    56
#define CHN   512
#define IN_DIM (CIN*HH*WW)      // 200704
#define NKEEP 128
#define SPLITK 64
#define KC (IN_DIM/SPLITK)      // 3136

typedef unsigned long long ull;

__device__ __forceinline__ ull pack2(float lo, float hi) {
    ull r;
    asm("mov.b64 %0, {%1,%2};" : "=l"(r) : "f"(lo), "f"(hi));
    return r;
}
__device__ __forceinline__ float2 unpack2(ull v) {
    float2 f;
    asm("mov.b64 {%0,%1}, %2;" : "=f"(f.x), "=f"(f.y) : "l"(v));
    return f;
}
__device__ __forceinline__ void fma2(ull& d, ull a, ull b) {
    asm("fma.rn.f32x2 %0, %1, %2, %0;" : "+l"(d) : "l"(a), "l"(b));
}

// Scratch (no allocations allowed -> __device__ globals)
__device__ float g_partial[SPLITK * BB * CHN];  // [s][m][n]  8 MB
__device__ float g_scores[BB * CHN];
__device__ int   g_idx[BB * NKEEP];

// ---------------------------------------------------------------------------
// Kernel 1: router GEMM partials via packed f32x2 FMA.
// scores[m,n] = sum_k x[m,k]*rw[n,k].  Split-K grid (8 n-tiles, 64 k-splits).
// 256 threads, 64x64 tile, per-thread 4m x 4n (= 4m x 2 f32x2), BK=16.
// A staged pre-duplicated {a,a} so the broadcast needs no pack ALU.
// ---------------------------------------------------------------------------
__global__ __launch_bounds__(256) void router_gemm(const float* __restrict__ x,
                                                   const float* __restrict__ rw) {
    const int nt = blockIdx.x;   // 0..7
    const int s  = blockIdx.y;   // 0..63
    __shared__ __align__(16) ull   As2[16][64];   // [k][m] duplicated pairs
    __shared__ __align__(16) float Bs[16][68];

    const int tid = threadIdx.x;
    const int tx = tid & 15;     // n lane
    const int ty = tid >> 4;     // m lane
    const int lm = tid >> 2;     // 0..63 row for loads
    const int lk = (tid & 3) * 4;

    const float* xp = x  + (size_t)lm * IN_DIM + (size_t)s * KC;
    const float* wp = rw + (size_t)(nt * 64 + lm) * IN_DIM + (size_t)s * KC;

    ull acc[4][2];
#pragma unroll
    for (int i = 0; i < 4; i++) { acc[i][0] = 0ull; acc[i][1] = 0ull; }

    for (int k0 = 0; k0 < KC; k0 += 16) {
        float4 av = *(const float4*)(xp + k0 + lk);
        float4 bv = *(const float4*)(wp + k0 + lk);
        __syncthreads();
        As2[lk + 0][lm] = pack2(av.x, av.x);
        As2[lk + 1][lm] = pack2(av.y, av.y);
        As2[lk + 2][lm] = pack2(av.z, av.z);
        As2[lk + 3][lm] = pack2(av.w, av.w);
        Bs[lk + 0][lm] = bv.x; Bs[lk + 1][lm] = bv.y;
        Bs[lk + 2][lm] = bv.z; Bs[lk + 3][lm] = bv.w;
        __syncthreads();
#pragma unroll
        for (int kk = 0; kk < 16; kk++) {
            ulonglong2 aa0 = *(const ulonglong2*)&As2[kk][ty * 4];
            ulonglong2 aa1 = *(const ulonglong2*)&As2[kk][ty * 4 + 2];
            float4 bvec = *(const float4*)&Bs[kk][tx * 4];
            ull b0 = pack2(bvec.x, bvec.y);
            ull b1 = pack2(bvec.z, bvec.w);
            fma2(acc[0][0], aa0.x, b0); fma2(acc[0][1], aa0.x, b1);
            fma2(acc[1][0], aa0.y, b0); fma2(acc[1][1], aa0.y, b1);
            fma2(acc[2][0], aa1.x, b0); fma2(acc[2][1], aa1.x, b1);
            fma2(acc[3][0], aa1.y, b0); fma2(acc[3][1], aa1.y, b1);
        }
    }
#pragma unroll
    for (int i = 0; i < 4; i++) {
        int m = ty * 4 + i;
        int n = nt * 64 + tx * 4;
        float2 lo = unpack2(acc[i][0]);
        float2 hi = unpack2(acc[i][1]);
        float4 v = make_float4(lo.x, lo.y, hi.x, hi.y);
        *(float4*)&g_partial[((size_t)s * BB + m) * CHN + n] = v;
    }
}

// ---------------------------------------------------------------------------
// Kernel 2: reduce split-K partials + bias -> g_scores[m][n]
// ---------------------------------------------------------------------------
__global__ void reduce_scores(const float* __restrict__ rb) {
    int t = blockIdx.x * 256 + threadIdx.x;   // 0 .. 64*512-1
    int m = t >> 9;
    int n = t & 511;
    float sum = rb[n];
    for (int s = 0; s < SPLITK; s++)
        sum += g_partial[((size_t)s * BB + m) * CHN + n];
    g_scores[t] = sum;
}

// ---------------------------------------------------------------------------
// Kernel 3: per-row stable top-128 by |score| -> sorted channel indices.
// rank_i = #{j : |s_j|>|s_i| or (|s_j|==|s_i| and j<i)}  (jax top_k tie rule)
// ---------------------------------------------------------------------------
__global__ __launch_bounds__(CHN) void select_topk() {
    __shared__ float sa[CHN];
    __shared__ unsigned char keep[CHN];
    const int m = blockIdx.x;
    const int i = threadIdx.x;
    float v = fabsf(g_scores[m * CHN + i]);
    sa[i] = v;
    __syncthreads();
    int rank = 0;
    for (int j = 0; j < CHN; j++) {
        float u = sa[j];
        rank += (u > v) || (u == v && j < i);
    }
    keep[i] = (rank < NKEEP) ? 1 : 0;
    __syncthreads();
    if (keep[i]) {
        int pos = 0;
        for (int j = 0; j < i; j++) pos += keep[j];
        g_idx[m * NKEEP + pos] = i;
    }
}

// ---------------------------------------------------------------------------
// Kernel 4: direct 3x3 conv for the 128 SELECTED channels, f32x2 packed.
// Block = 128 threads: (h-tile of 8 rows, 8 selected channels, batch b).
// Compute threads 0..111: group g (4 chans) x 56 spatial threads, each owns a
// 4(chan) x 2(row) x 2(f32x2 col-pair) tile -> 144 FMA2 per ci step.
// Weights staged in smem pre-duplicated {w,w}; x col-pairs via LDS.64 with
// only 2 odd-shift packs per row.
// ---------------------------------------------------------------------------
__global__ __launch_bounds__(128) void conv_sel(const float* __restrict__ x,
                                                const float* __restrict__ cw,
                                                const float* __restrict__ cb,
                                                float* __restrict__ out) {
    const int ht = blockIdx.x;   // 0..6   h0 = ht*8
    const int jg = blockIdx.y;   // 0..15  channels jg*8 .. jg*8+7
    const int b  = blockIdx.z;

    __shared__ __align__(16) float xs[8][10][58];   // [ci][row(+halo)][col(+halo)]
    __shared__ __align__(16) ull   ws2[8][8][9];    // [ch][ci][tap] {w,w}
    __shared__ int   cidx[8];
    __shared__ float cbias[8];

    const int tid = threadIdx.x;
    if (tid < 8) {
        int c = g_idx[b * NKEEP + jg * 8 + tid];
        cidx[tid]  = c;
        cbias[tid] = cb[c];
    }

    const int h0 = ht * 8;
    const bool compute = tid < 112;
    const int g  = tid / 56;         // channel sub-group (0/1)
    const int t  = tid - g * 56;
    const int wc = t % 14;           // col group (4 cols = 2 pairs)
    const int hr = t / 14;           // row group (2 rows), 0..3

    ull acc[4][2][2];
#pragma unroll
    for (int ch = 0; ch < 4; ch++)
#pragma unroll
        for (int r = 0; r < 2; r++) { acc[ch][r][0] = 0ull; acc[ch][r][1] = 0ull; }

    for (int c0 = 0; c0 < CIN; c0 += 8) {
        __syncthreads();
        // stage x slab: 8 ci x 10 rows x 58 cols, zero-padded halo
        for (int i = tid; i < 8 * 10 * 58; i += 128) {
            int ci  = i / 580;
            int rem = i - ci * 580;
            int r   = rem / 58;
            int col = rem - r * 58;
            int h  = h0 - 1 + r;
            int w  = col - 1;
            float v = 0.f;
            if ((unsigned)h < (unsigned)HH && (unsigned)w < (unsigned)WW)
                v = x[(((size_t)b * CIN + c0 + ci) * HH + h) * WW + w];
            xs[ci][r][col] = v;
        }
        // stage weights duplicated: 8 chans x 8 ci x 9 taps
        for (int i = tid; i < 576; i += 128) {
            int ch  = i / 72;
            int rem = i - ch * 72;
            float w = cw[((size_t)cidx[ch] * CIN + c0) * 9 + rem];
            ws2[ch][rem / 9][rem % 9] = pack2(w, w);
        }
        __syncthreads();

        if (compute) {
#pragma unroll
            for (int ci = 0; ci < 8; ci++) {
                // x pairs: xp[r][start] = cols (start, start+1), start 0..4
                ull xp[4][5];
#pragma unroll
                for (int r = 0; r < 4; r++) {
                    const float* xr = &xs[ci][hr * 2 + r][wc * 4];
                    float2 f01 = *(const float2*)(xr + 0);
                    float2 f23 = *(const float2*)(xr + 2);
                    float2 f45 = *(const float2*)(xr + 4);
                    xp[r][0] = pack2(f01.x, f01.y);
                    xp[r][2] = pack2(f23.x, f23.y);
                    xp[r][4] = pack2(f45.x, f45.y);
                    xp[r][1] = pack2(f01.y, f23.x);
                    xp[r][3] = pack2(f23.y, f45.x);
                }
#pragma unroll
                for (int ch = 0; ch < 4; ch++) {
#pragma unroll
                    for (int kh = 0; kh < 3; kh++) {
#pragma unroll
                        for (int kw = 0; kw < 3; kw++) {
                            ull wv = ws2[g * 4 + ch][ci][kh * 3 + kw];
                            fma2(acc[ch][0][0], xp[0 + kh][0 + kw], wv);
                            fma2(acc[ch][0][1], xp[0 + kh][2 + kw], wv);
                            fma2(acc[ch][1][0], xp[1 + kh][0 + kw], wv);
                            fma2(acc[ch][1][1], xp[1 + kh][2 + kw], wv);
                        }
                    }
                }
            }
        }
    }

    if (compute) {
#pragma unroll
        for (int ch = 0; ch < 4; ch++) {
            int j = jg * 8 + g * 4 + ch;
            float bias = cbias[g * 4 + ch];
#pragma unroll
            for (int r = 0; r < 2; r++) {
                int h = h0 + hr * 2 + r;
                float* op = out + (((size_t)b * NKEEP + j) * HH + h) * WW + wc * 4;
#pragma unroll
                for (int c2 = 0; c2 < 2; c2++) {
                    float2 v = unpack2(acc[ch][r][c2]);
                    v.x += bias; v.y += bias;
                    *(float2*)(op + c2 * 2) = v;
                }
            }
        }
    }
}

// ---------------------------------------------------------------------------
extern "C" void kernel_launch(void* const* d_in, const int* in_sizes, int n_in,
                              void* d_out, int out_size) {
    const float* x  = (const float*)d_in[0];   // [64,64,56,56]
    const float* cw = (const float*)d_in[1];   // [4,128,64,3,3] == [512,64,3,3]
    const float* cb = (const float*)d_in[2];   // [4,128] == [512]
    const float* rw = (const float*)d_in[3];   // [512, 200704]
    const float* rb = (const float*)d_in[4];   // [512]
    float* out = (float*)d_out;                // [64,128,56,56]

    router_gemm<<<dim3(8, SPLITK), 256>>>(x, rw);
    reduce_scores<<<(BB * CHN) / 256, 256>>>(rb);
    select_topk<<<BB, CHN>>>();
    conv_sel<<<dim3(7, 16, BB), 128>>>(x, cw, cb, out);
}

// round 4
// speedup vs baseline: 1.6551x; 1.6233x over previous
#include <cuda_runtime.h>
#include <cstdint>

#define BB    64
#define CIN   64
#define HH    56
#define WW    56
#define CHN   512
#define IN_DIM (CIN*HH*WW)      // 200704
#define NKEEP 128
#define SPLITK 64
#define KC (IN_DIM/SPLITK)      // 3136
#define SPAT (HH*WW)            // 3136
#define NTILES 25               // ceil(3136/128)
#define KCHUNKS 18              // 9 taps * 2 ci-halves of 32

typedef unsigned long long ull;

// ---------------- small helpers ----------------
__device__ __forceinline__ ull pack2(float lo, float hi) {
    ull r; asm("mov.b64 %0, {%1,%2};" : "=l"(r) : "f"(lo), "f"(hi)); return r;
}
__device__ __forceinline__ float2 unpack2(ull v) {
    float2 f; asm("mov.b64 {%0,%1}, %2;" : "=f"(f.x), "=f"(f.y) : "l"(v)); return f;
}
__device__ __forceinline__ void fma2(ull& d, ull a, ull b) {
    asm("fma.rn.f32x2 %0, %1, %2, %0;" : "+l"(d) : "l"(a), "l"(b));
}
__device__ __forceinline__ float to_tf32(float f) {
    uint32_t u; asm("cvt.rna.tf32.f32 %0, %1;" : "=r"(u) : "f"(f));
    return __uint_as_float(u);
}
// tf32 tensor-core MMA (sm_80+ baseline PTX -> works on base sm_103 target)
__device__ __forceinline__ void mma_tf32(float* c, const uint32_t* a, const uint32_t* b) {
    asm volatile(
        "mma.sync.aligned.m16n8k8.row.col.f32.tf32.tf32.f32 "
        "{%0,%1,%2,%3}, {%4,%5,%6,%7}, {%8,%9}, {%0,%1,%2,%3};"
        : "+f"(c[0]), "+f"(c[1]), "+f"(c[2]), "+f"(c[3])
        : "r"(a[0]), "r"(a[1]), "r"(a[2]), "r"(a[3]), "r"(b[0]), "r"(b[1]));
}

// ---------------- scratch (__device__ globals; no allocs allowed) ----------
__device__ float g_partial[SPLITK * BB * CHN];  // 8 MB
__device__ float g_scores[BB * CHN];
__device__ int   g_idx[BB * NKEEP];
__device__ float g_xt[(size_t)BB * SPAT * CIN];   // x channels-last, tf32-rounded
__device__ float g_bw[(size_t)BB * NKEEP * 576];  // gathered weights [b][n][tap*64+ci]

// ---------------------------------------------------------------------------
// Kernel 1: router GEMM partials via packed f32x2 FMA (exact fp32).
// ---------------------------------------------------------------------------
__global__ __launch_bounds__(256) void router_gemm(const float* __restrict__ x,
                                                   const float* __restrict__ rw) {
    const int nt = blockIdx.x;
    const int s  = blockIdx.y;
    __shared__ __align__(16) ull   As2[16][64];
    __shared__ __align__(16) float Bs[16][68];

    const int tid = threadIdx.x;
    const int tx = tid & 15;
    const int ty = tid >> 4;
    const int lm = tid >> 2;
    const int lk = (tid & 3) * 4;

    const float* xp = x  + (size_t)lm * IN_DIM + (size_t)s * KC;
    const float* wp = rw + (size_t)(nt * 64 + lm) * IN_DIM + (size_t)s * KC;

    ull acc[4][2];
#pragma unroll
    for (int i = 0; i < 4; i++) { acc[i][0] = 0ull; acc[i][1] = 0ull; }

    for (int k0 = 0; k0 < KC; k0 += 16) {
        float4 av = *(const float4*)(xp + k0 + lk);
        float4 bv = *(const float4*)(wp + k0 + lk);
        __syncthreads();
        As2[lk + 0][lm] = pack2(av.x, av.x);
        As2[lk + 1][lm] = pack2(av.y, av.y);
        As2[lk + 2][lm] = pack2(av.z, av.z);
        As2[lk + 3][lm] = pack2(av.w, av.w);
        Bs[lk + 0][lm] = bv.x; Bs[lk + 1][lm] = bv.y;
        Bs[lk + 2][lm] = bv.z; Bs[lk + 3][lm] = bv.w;
        __syncthreads();
#pragma unroll
        for (int kk = 0; kk < 16; kk++) {
            ulonglong2 aa0 = *(const ulonglong2*)&As2[kk][ty * 4];
            ulonglong2 aa1 = *(const ulonglong2*)&As2[kk][ty * 4 + 2];
            float4 bvec = *(const float4*)&Bs[kk][tx * 4];
            ull b0 = pack2(bvec.x, bvec.y);
            ull b1 = pack2(bvec.z, bvec.w);
            fma2(acc[0][0], aa0.x, b0); fma2(acc[0][1], aa0.x, b1);
            fma2(acc[1][0], aa0.y, b0); fma2(acc[1][1], aa0.y, b1);
            fma2(acc[2][0], aa1.x, b0); fma2(acc[2][1], aa1.x, b1);
            fma2(acc[3][0], aa1.y, b0); fma2(acc[3][1], aa1.y, b1);
        }
    }
#pragma unroll
    for (int i = 0; i < 4; i++) {
        int m = ty * 4 + i;
        int n = nt * 64 + tx * 4;
        float2 lo = unpack2(acc[i][0]);
        float2 hi = unpack2(acc[i][1]);
        float4 v = make_float4(lo.x, lo.y, hi.x, hi.y);
        *(float4*)&g_partial[((size_t)s * BB + m) * CHN + n] = v;
    }
}

// ---------------------------------------------------------------------------
// Kernel 2: reduce split-K partials + bias
// ---------------------------------------------------------------------------
__global__ void reduce_scores(const float* __restrict__ rb) {
    int t = blockIdx.x * 256 + threadIdx.x;
    int m = t >> 9;
    int n = t & 511;
    float sum = rb[n];
    for (int s = 0; s < SPLITK; s++)
        sum += g_partial[((size_t)s * BB + m) * CHN + n];
    g_scores[t] = sum;
}

// ---------------------------------------------------------------------------
// Kernel 3: per-row stable top-128 by |score| (jax tie rule), sorted indices
// ---------------------------------------------------------------------------
__global__ __launch_bounds__(CHN) void select_topk() {
    __shared__ float sa[CHN];
    __shared__ unsigned char keep[CHN];
    const int m = blockIdx.x;
    const int i = threadIdx.x;
    float v = fabsf(g_scores[m * CHN + i]);
    sa[i] = v;
    __syncthreads();
    int rank = 0;
    for (int j = 0; j < CHN; j++) {
        float u = sa[j];
        rank += (u > v) || (u == v && j < i);
    }
    keep[i] = (rank < NKEEP) ? 1 : 0;
    __syncthreads();
    if (keep[i]) {
        int pos = 0;
        for (int j = 0; j < i; j++) pos += keep[j];
        g_idx[m * NKEEP + pos] = i;
    }
}

// ---------------------------------------------------------------------------
// Kernel T: transpose x to channels-last, rounding to tf32.
// x[b][ci][s] -> g_xt[b][s][ci]
// ---------------------------------------------------------------------------
__global__ __launch_bounds__(256) void transpose_x(const float* __restrict__ x) {
    __shared__ float tile[32][33];
    const int s0 = blockIdx.x * 32;
    const int c0 = blockIdx.y * 32;
    const int b  = blockIdx.z;
    const int tx = threadIdx.x;
    const int ty = threadIdx.y;
#pragma unroll
    for (int k = 0; k < 4; k++) {
        int ci = c0 + ty + k * 8;
        tile[ty + k * 8][tx] = x[((size_t)b * CIN + ci) * SPAT + s0 + tx];
    }
    __syncthreads();
#pragma unroll
    for (int k = 0; k < 4; k++) {
        int srow = s0 + ty + k * 8;
        g_xt[((size_t)b * SPAT + srow) * CIN + c0 + tx] = to_tf32(tile[tx][ty + k * 8]);
    }
}

// ---------------------------------------------------------------------------
// Kernel G: gather selected-channel weights per sample, K-reordered + tf32.
// g_bw[b][n][tap*64 + ci] = cw[cidx][ci][tap]
// ---------------------------------------------------------------------------
__global__ __launch_bounds__(192) void gather_w(const float* __restrict__ cw) {
    const int n = blockIdx.x;
    const int b = blockIdx.y;
    const int c = g_idx[b * NKEEP + n];
    const float* src = cw + (size_t)c * 576;
    float* dst = g_bw + ((size_t)(b * NKEEP + n)) * 576;
    for (int t = threadIdx.x; t < 576; t += 192)
        dst[t] = to_tf32(src[(t & 63) * 9 + (t >> 6)]);
}

// ---------------------------------------------------------------------------
// Kernel 4: conv as implicit GEMM on tensor cores via mma.sync tf32 m16n8k8.
// Block (tile t, batch b), 256 thr (8 warps, 2m x 4n). Per block:
//   D[128 spatial][128 sel ch] = sum over K=576 (18 chunks of 32).
// A/B staged in smem in fragment-native layout; mainloop = LDS.128 + HMMA.
// ---------------------------------------------------------------------------
__global__ __launch_bounds__(256) void conv_mma(const float* __restrict__ cb,
                                                float* __restrict__ out) {
    // sA[(mtile*4 + k8)*32 + lane][4 slots] ; sB[(ntile*4 + k8)*32 + lane][2 slots]
    __shared__ __align__(16) float sA[8 * 4 * 32 * 4];    // 16 KB
    __shared__ __align__(16) float sB[16 * 4 * 32 * 2];   // 16 KB
    __shared__ float sbias[NKEEP];

    const int tid  = threadIdx.x;
    const int lane = tid & 31;
    const int wid  = tid >> 5;
    const int wm   = wid & 1;     // m half (64 rows)
    const int wn   = wid >> 1;    // n quarter (32 cols)
    const int t = blockIdx.x;
    const int b = blockIdx.y;

    if (tid < NKEEP) sbias[tid] = cb[g_idx[b * NKEEP + tid]];

    // staging role: row m_row of A and B, 16-wide k segment
    const int m_row = tid >> 1;          // 0..127
    const int ks    = (tid & 1) * 16;    // 0 or 16
    const int s  = t * 128 + m_row;      // spatial position for A row
    const int hh = s / WW;
    const int ww = s % WW;
    const float* bsrc = g_bw + ((size_t)(b * NKEEP + m_row)) * 576 + ks;

    // precomputed scatter bases (row-dependent parts)
    const int a_mt  = m_row >> 4;
    const int a_row = m_row & 15;
    const int a_laneb = (a_row & 7) << 2;
    const int a_slotb = a_row >> 3;
    const int b_nt  = m_row >> 3;
    const int b_nin = m_row & 7;

    float acc[4][4][4];
#pragma unroll
    for (int mt = 0; mt < 4; mt++)
#pragma unroll
        for (int nt = 0; nt < 4; nt++)
#pragma unroll
            for (int r = 0; r < 4; r++) acc[mt][nt][r] = 0.f;

    for (int kc = 0; kc < KCHUNKS; kc++) {
        const int tap = kc >> 1;
        const int hc  = kc & 1;
        const int hp = hh + tap / 3 - 1;
        const int wp = ww + tap % 3 - 1;
        const bool valid = (s < SPAT) && ((unsigned)hp < (unsigned)HH) &&
                           ((unsigned)wp < (unsigned)WW);
        float av[16], bv[16];
        if (valid) {
            const float* asrc = g_xt + (((size_t)b * SPAT + hp * WW + wp) << 6) + hc * 32 + ks;
#pragma unroll
            for (int i = 0; i < 4; i++) *(float4*)&av[i * 4] = *(const float4*)(asrc + i * 4);
        } else {
#pragma unroll
            for (int i = 0; i < 16; i++) av[i] = 0.f;
        }
#pragma unroll
        for (int i = 0; i < 4; i++) *(float4*)&bv[i * 4] = *(const float4*)(bsrc + kc * 32 + i * 4);

        __syncthreads();   // previous compute done before overwrite
        // scatter A into fragment layout
#pragma unroll
        for (int i = 0; i < 16; i++) {
            int k  = ks + i;
            int k8 = k >> 3, col = k & 7;
            int lanei = a_laneb | (col & 3);
            int sloti = a_slotb | ((col >> 2) << 1);
            sA[((((a_mt << 2) | k8) << 5) | lanei) * 4 + sloti] = av[i];
        }
        // scatter B into fragment layout
#pragma unroll
        for (int i = 0; i < 16; i++) {
            int k  = ks + i;
            int k8 = k >> 3, kin = k & 7;
            int lanei = (b_nin << 2) | (kin & 3);
            int sloti = kin >> 2;
            sB[((((b_nt << 2) | k8) << 5) | lanei) * 2 + sloti] = bv[i];
        }
        __syncthreads();

        // mainloop: 4 k8 steps x (4 mt x 4 nt) MMAs
#pragma unroll
        for (int k8 = 0; k8 < 4; k8++) {
            uint32_t af[4][4];
#pragma unroll
            for (int mt = 0; mt < 4; mt++) {
                float4 v = *(const float4*)&sA[((((wm * 4 + mt) << 2) | k8) << 5 | lane) * 4];
                af[mt][0] = __float_as_uint(v.x); af[mt][1] = __float_as_uint(v.y);
                af[mt][2] = __float_as_uint(v.z); af[mt][3] = __float_as_uint(v.w);
            }
            uint32_t bf[4][2];
#pragma unroll
            for (int nt = 0; nt < 4; nt++) {
                float2 v = *(const float2*)&sB[((((wn * 4 + nt) << 2) | k8) << 5 | lane) * 2];
                bf[nt][0] = __float_as_uint(v.x); bf[nt][1] = __float_as_uint(v.y);
            }
#pragma unroll
            for (int mt = 0; mt < 4; mt++)
#pragma unroll
                for (int nt = 0; nt < 4; nt++)
                    mma_tf32(acc[mt][nt], af[mt], bf[nt]);
        }
    }

    // epilogue: bias + store. c0:(r,c) c1:(r,c+1) c2:(r+8,c) c3:(r+8,c+1)
    const int row0 = lane >> 2;
    const int col0 = (lane & 3) * 2;
#pragma unroll
    for (int mt = 0; mt < 4; mt++) {
#pragma unroll
        for (int nt = 0; nt < 4; nt++) {
            int n  = wn * 32 + nt * 8 + col0;
            int sr = t * 128 + wm * 64 + mt * 16 + row0;
            float b0 = sbias[n], b1 = sbias[n + 1];
            float* op0 = out + ((size_t)b * NKEEP + n) * SPAT;
            float* op1 = op0 + SPAT;
            if (sr < SPAT) {
                op0[sr] = acc[mt][nt][0] + b0;
                op1[sr] = acc[mt][nt][1] + b1;
            }
            if (sr + 8 < SPAT) {
                op0[sr + 8] = acc[mt][nt][2] + b0;
                op1[sr + 8] = acc[mt][nt][3] + b1;
            }
        }
    }
}

// ---------------------------------------------------------------------------
extern "C" void kernel_launch(void* const* d_in, const int* in_sizes, int n_in,
                              void* d_out, int out_size) {
    const float* x  = (const float*)d_in[0];   // [64,64,56,56]
    const float* cw = (const float*)d_in[1];   // [512,64,3,3]
    const float* cb = (const float*)d_in[2];   // [512]
    const float* rw = (const float*)d_in[3];   // [512,200704]
    const float* rb = (const float*)d_in[4];   // [512]
    float* out = (float*)d_out;                // [64,128,56,56]

    transpose_x<<<dim3(SPAT / 32, CIN / 32, BB), dim3(32, 8)>>>(x);
    router_gemm<<<dim3(8, SPLITK), 256>>>(x, rw);
    reduce_scores<<<(BB * CHN) / 256, 256>>>(rb);
    select_topk<<<BB, CHN>>>();
    gather_w<<<dim3(NKEEP, BB), 192>>>(cw);
    conv_mma<<<dim3(NTILES, BB), 256>>>(cb, out);
}